// round 8
// baseline (speedup 1.0000x reference)
#include <cuda_runtime.h>

// Grouping: out[b,g,h] = sum_{i=0..3} feats[b, 4g+i, h] * values[b*S + 4g + i]
// B=16, S=4096, G=1024, H=768. Pure HBM streaming, at DRAM roofline
// (82.6% of 8TB/s stable across all structural variants; 252 MB irreducible).
// R8: final efficiency probe — add .L2::256B prefetch-size qualifier to the
// streaming loads (coarser LTS fetch granularity for the read stream).
// Otherwise identical to the R6/R7 winner (x1 float4/thread, .cs hints).

#define B_DIM 16
#define G_DIM 1024
#define H_DIM 768
#define H4    (H_DIM / 4)   // 192 float4 per row
#define BLOCK 512

__device__ __forceinline__ float4 ldcs_l2_256(const float4* __restrict__ p) {
    float4 v;
    asm volatile("ld.global.cs.L2::256B.v4.f32 {%0,%1,%2,%3}, [%4];"
                 : "=f"(v.x), "=f"(v.y), "=f"(v.z), "=f"(v.w)
                 : "l"(p));
    return v;
}

__global__ __launch_bounds__(BLOCK)
void grouping_kernel(const float4* __restrict__ feats,
                     const float4* __restrict__ vals,   // values viewed as float4[B*G]
                     float4* __restrict__ out) {
    // total = B*G*H4 = 3,145,728 threads; exact grid, no bounds check
    const unsigned idx = blockIdx.x * blockDim.x + threadIdx.x;
    const unsigned h  = idx % H4;
    const unsigned bg = idx / H4;                  // flat output row: b*G + g

    // feats row base (float4 units): 4*bg*H4 + h  (< 2^24, fits 32-bit)
    const float4* __restrict__ base = feats + 4u * bg * H4 + h;

    const float4 w = __ldg(&vals[bg]);             // per-group weights (reused -> cached)

    // 4 independent front-batched streaming loads, 256B L2 fetch granularity
    const float4 a = ldcs_l2_256(base + 0 * H4);
    const float4 b = ldcs_l2_256(base + 1 * H4);
    const float4 c = ldcs_l2_256(base + 2 * H4);
    const float4 d = ldcs_l2_256(base + 3 * H4);

    float4 o;
    o.x = w.x * a.x + w.y * b.x + w.z * c.x + w.w * d.x;
    o.y = w.x * a.y + w.y * b.y + w.z * c.y + w.w * d.y;
    o.z = w.x * a.z + w.y * b.z + w.z * c.z + w.w * d.z;
    o.w = w.x * a.w + w.y * b.w + w.z * c.w + w.w * d.w;

    __stcs(out + bg * (unsigned)H4 + h, o);
}

extern "C" void kernel_launch(void* const* d_in, const int* in_sizes, int n_in,
                              void* d_out, int out_size) {
    // metadata order: feats [B,S,H] f32, indices [3, B*S] i64 (closed-form, unused),
    // values [B*S] f32, output [B,G,H] f32
    const float4* feats = (const float4*)d_in[0];
    const float4* vals  = (const float4*)d_in[2];
    float4* out = (float4*)d_out;

    const unsigned total = B_DIM * G_DIM * H4;   // 3,145,728
    const int blocks = total / BLOCK;            // 6144, exact
    grouping_kernel<<<blocks, BLOCK>>>(feats, vals, out);
}